// round 14
// baseline (speedup 1.0000x reference)
#include <cuda_runtime.h>
#include <cuda_fp16.h>
#include <cstdint>

// ---------------- Problem constants ----------------
#define N_TOK (16 * 2048)   // 32768 tokens
#define D_IN  512
#define E_DIM 256
#define H_DIM 1024
#define NE    4
#define RIN   (E_DIM + D_IN)
#define EPSV  1e-10f

// ---------------- GEMM tiling ----------------
#define TM 128
#define TN 128
#define KC 64                         // K elements per chunk (64 fp16 = 128B/row)
#define STAGES 6
#define NTHREADS 256

#define RTOK_PER_BLK 8
#define RBLK (N_TOK / RTOK_PER_BLK)

// ---------------- Shared memory layout ----------------
// Per stage: A 16K | B 16K = 32K
#define STAGE_BYTES 32768
#define SM_BIAS  (STAGES * STAGE_BYTES)          // 196608: 128 floats
#define SM_ABASE (SM_BIAS + 512)                 // 128 x int64 row byte offsets
#define SM_TOK   (SM_ABASE + 1024)               // 128 x int
#define SMEM_DYN (SM_TOK + 512)                  // ~198656 bytes

// ---------------- Device scratch ----------------
__device__ int   g_gate_idx[N_TOK];
__device__ float g_gate_val[N_TOK];
__device__ int   g_perm[N_TOK + 128];
__device__ int   g_cnt[NE];
__device__ int   g_cur[NE];
__device__ int   g_off[NE + 1];
__device__ int   g_tile_start[NE + 1];
__device__ float g_part_l1[RBLK];
__device__ float g_part_imp[RBLK * NE];

__device__ __half g_xh[(size_t)N_TOK * D_IN];
__device__ __half g_w1h[(size_t)NE * H_DIM * D_IN];
__device__ __half g_w2h[(size_t)NE * D_IN * H_DIM];
__device__ __half g_hh[(size_t)(N_TOK + 128) * H_DIM];

// ---------------- PTX helpers (baseline ISA only) ----------------
__device__ __forceinline__ uint32_t smem_u32(const void* p) {
    uint32_t a;
    asm("{ .reg .u64 t; cvta.to.shared.u64 t, %1; cvt.u32.u64 %0, t; }" : "=r"(a) : "l"(p));
    return a;
}
__device__ __forceinline__ void cp_async16(uint32_t dst, const void* src) {
    asm volatile("cp.async.cg.shared.global [%0], [%1], 16;" :: "r"(dst), "l"(src) : "memory");
}
#define CP_COMMIT() asm volatile("cp.async.commit_group;" ::: "memory")
// Pending groups held at STAGES-1 = 5 (dummy commits past the tail);
// wait_group 4 => the oldest group (chunk c) has completed.
#define CP_WAITP()  asm volatile("cp.async.wait_group 4;" ::: "memory")
#define CP_WAIT0()  asm volatile("cp.async.wait_group 0;" ::: "memory")

__device__ __forceinline__ void ldsm4(uint32_t* r, uint32_t addr) {
    asm volatile("ldmatrix.sync.aligned.m8n8.x4.shared.b16 {%0,%1,%2,%3}, [%4];"
        : "=r"(r[0]), "=r"(r[1]), "=r"(r[2]), "=r"(r[3]) : "r"(addr));
}
__device__ __forceinline__ void mma16816(float* c, const uint32_t* a, const uint32_t* b) {
    asm volatile(
        "mma.sync.aligned.m16n8k16.row.col.f32.f16.f16.f32 "
        "{%0,%1,%2,%3}, {%4,%5,%6,%7}, {%8,%9}, {%0,%1,%2,%3};"
        : "+f"(c[0]), "+f"(c[1]), "+f"(c[2]), "+f"(c[3])
        : "r"(a[0]), "r"(a[1]), "r"(a[2]), "r"(a[3]), "r"(b[0]), "r"(b[1]));
}
__device__ __forceinline__ uint32_t swz(uint32_t b) { return b ^ ((b >> 3) & 0x70); }

// ---------------- 1) router (+ fused x->fp16 AND w1/w2->fp16 conversion) -------
__global__ __launch_bounds__(256) void router_kernel(
    const float* __restrict__ x, const float* __restrict__ emb,
    const float* __restrict__ rw,
    const float4* __restrict__ w1g, const float4* __restrict__ w2g)
{
    __shared__ float s_rwt[NE][RIN];
    __shared__ float s_l1[RTOK_PER_BLK];
    __shared__ float s_imp[RTOK_PER_BLK][NE];

    int t = threadIdx.x;

    // fused weight conversion: one float4 per thread (4096 blk x 256 thr = 2*n4)
    {
        const int n4 = NE * H_DIM * D_IN / 4;
        int gi = blockIdx.x * 256 + t;
        if (gi == 0) {
            #pragma unroll
            for (int e = 0; e < NE; e++) { g_cnt[e] = 0; g_cur[e] = 0; }
        }
        if (gi < n4) {
            float4 v = w1g[gi];
            __half2* h = (__half2*)g_w1h;
            h[2 * gi]     = __floats2half2_rn(v.x, v.y);
            h[2 * gi + 1] = __floats2half2_rn(v.z, v.w);
        } else {
            int j = gi - n4;
            float4 v = w2g[j];
            __half2* h = (__half2*)g_w2h;
            h[2 * j]     = __floats2half2_rn(v.x, v.y);
            h[2 * j + 1] = __floats2half2_rn(v.z, v.w);
        }
    }

    for (int i = t; i < RIN * NE; i += blockDim.x) {
        int e = i / RIN, k = i % RIN;
        s_rwt[e][k] = rw[k * NE + e];
    }
    __syncthreads();

    int warp = t >> 5, lane = t & 31;
    int tok = blockIdx.x * RTOK_PER_BLK + warp;

    float acc0 = 0.f, acc1 = 0.f, acc2 = 0.f, acc3 = 0.f;
    const float4* er4 = (const float4*)(emb + (size_t)tok * E_DIM);
    const float4* xr4 = (const float4*)(x   + (size_t)tok * D_IN);
    __half2* xh2 = (__half2*)(g_xh + (size_t)tok * D_IN);

    const float* w0 = s_rwt[0];
    const float* w1 = s_rwt[1];
    const float* w2 = s_rwt[2];
    const float* w3 = s_rwt[3];

    #pragma unroll
    for (int i = 0; i < E_DIM / 128; i++) {
        int q = lane + 32 * i;
        float4 v = er4[q];
        int k = 4 * q;
        acc0 += v.x * w0[k] + v.y * w0[k + 1] + v.z * w0[k + 2] + v.w * w0[k + 3];
        acc1 += v.x * w1[k] + v.y * w1[k + 1] + v.z * w1[k + 2] + v.w * w1[k + 3];
        acc2 += v.x * w2[k] + v.y * w2[k + 1] + v.z * w2[k + 2] + v.w * w2[k + 3];
        acc3 += v.x * w3[k] + v.y * w3[k + 1] + v.z * w3[k + 2] + v.w * w3[k + 3];
    }
    #pragma unroll
    for (int i = 0; i < D_IN / 128; i++) {
        int q = lane + 32 * i;
        float4 v = xr4[q];
        int k = E_DIM + 4 * q;
        acc0 += v.x * w0[k] + v.y * w0[k + 1] + v.z * w0[k + 2] + v.w * w0[k + 3];
        acc1 += v.x * w1[k] + v.y * w1[k + 1] + v.z * w1[k + 2] + v.w * w1[k + 3];
        acc2 += v.x * w2[k] + v.y * w2[k + 1] + v.z * w2[k + 2] + v.w * w2[k + 3];
        acc3 += v.x * w3[k] + v.y * w3[k + 1] + v.z * w3[k + 2] + v.w * w3[k + 3];
        xh2[2 * q]     = __floats2half2_rn(v.x, v.y);
        xh2[2 * q + 1] = __floats2half2_rn(v.z, v.w);
    }

    #pragma unroll
    for (int o = 16; o; o >>= 1) {
        acc0 += __shfl_xor_sync(0xFFFFFFFFu, acc0, o);
        acc1 += __shfl_xor_sync(0xFFFFFFFFu, acc1, o);
        acc2 += __shfl_xor_sync(0xFFFFFFFFu, acc2, o);
        acc3 += __shfl_xor_sync(0xFFFFFFFFu, acc3, o);
    }

    if (lane == 0) {
        float lg[NE] = {acc0, acc1, acc2, acc3};
        float m = lg[0];
        #pragma unroll
        for (int e = 1; e < NE; e++) m = fmaxf(m, lg[e]);
        float p[NE], s = 0.f;
        #pragma unroll
        for (int e = 0; e < NE; e++) { p[e] = __expf(lg[e] - m); s += p[e]; }
        float inv = 1.f / s;
        float sump = 0.f, sq = 0.f;
        float best = -1.f; int bi = 0;
        #pragma unroll
        for (int e = 0; e < NE; e++) {
            p[e] *= inv;
            sump += p[e];
            sq   += p[e] * p[e];
            if (p[e] > best) { best = p[e]; bi = e; }
        }
        g_gate_idx[tok] = bi;
        g_gate_val[tok] = best;
        atomicAdd(&g_cnt[bi], 1);
        s_l1[warp] = sump / (sqrtf(sq) + EPSV);
        #pragma unroll
        for (int e = 0; e < NE; e++) s_imp[warp][e] = p[e];
    }
    __syncthreads();
    if (t == 0) {
        float a = 0.f;
        #pragma unroll
        for (int w = 0; w < RTOK_PER_BLK; w++) a += s_l1[w];
        g_part_l1[blockIdx.x] = a;
    }
    if (t < NE) {
        float a = 0.f;
        #pragma unroll
        for (int w = 0; w < RTOK_PER_BLK; w++) a += s_imp[w][t];
        g_part_imp[blockIdx.x * NE + t] = a;
    }
}

// ---------------- 2) finalize ----------------
__global__ void finalize_kernel(float* __restrict__ out, int out_size) {
    __shared__ float sh[256];
    int t = threadIdx.x;
    float v[5] = {0.f, 0.f, 0.f, 0.f, 0.f};
    for (int b = t; b < RBLK; b += 256) {
        v[0] += g_part_l1[b];
        #pragma unroll
        for (int e = 0; e < NE; e++) v[1 + e] += g_part_imp[b * NE + e];
    }
    float res[5];
    #pragma unroll
    for (int q = 0; q < 5; q++) {
        sh[t] = v[q]; __syncthreads();
        for (int s = 128; s; s >>= 1) {
            if (t < s) sh[t] += sh[t + s];
            __syncthreads();
        }
        res[q] = sh[0];
        __syncthreads();
    }
    if (t == 0) {
        float l1 = res[0] / (float)N_TOK;
        float mean = (res[1] + res[2] + res[3] + res[4]) * 0.25f;
        float var = 0.f;
        #pragma unroll
        for (int e = 0; e < NE; e++) {
            float d = res[1 + e] - mean;
            var += d * d;
        }
        var *= 0.25f;
        float imp = var / (mean * mean + EPSV);
        if (out_size >= N_TOK * D_IN + 2) {
            out[N_TOK * D_IN]     = l1;
            out[N_TOK * D_IN + 1] = imp;
        }
        int s = 0, ts = 0;
        #pragma unroll
        for (int e = 0; e < NE; e++) {
            g_off[e] = s;
            g_tile_start[e] = ts;
            s  += g_cnt[e];
            ts += (g_cnt[e] + TM - 1) / TM;
        }
        g_off[NE] = s;
        g_tile_start[NE] = ts;
    }
}

// ---------------- 3) scatter (warp-aggregated atomics) ----------------
__global__ void scatter_kernel() {
    int t = blockIdx.x * blockDim.x + threadIdx.x;
    int lane = threadIdx.x & 31;
    int e = g_gate_idx[t];
    #pragma unroll
    for (int ei = 0; ei < NE; ei++) {
        unsigned m = __ballot_sync(0xFFFFFFFFu, e == ei);
        if (e == ei) {
            int leader = __ffs(m) - 1;
            int rank = __popc(m & ((1u << lane) - 1));
            int base = 0;
            if (lane == leader) base = atomicAdd(&g_cur[ei], __popc(m));
            base = __shfl_sync(m, base, leader);
            g_perm[g_off[ei] + base + rank] = t;
        }
    }
}

// ---------------- 4/5) persistent fp16 grouped GEMM via mma.sync ----------------
// 128x128 CTA tile, 8 warps (2 M x 4 N), warp tile 64x32, 6-stage cp.async
// pipeline, fragment double-buffering (ldsm of ks+1 overlaps mma of ks).
// FIRST:  H = relu(X[perm] @ W1^T + b1)  (fp16 out)   KDIM=512,  NOUT=1024
// !FIRST: out[tok] = gate * (H @ W2^T + b2)  (f32)    KDIM=1024, NOUT=512
template <int KDIM, int NOUT, bool FIRST>
__global__ __launch_bounds__(NTHREADS, 1) void moe_gemm(const float* __restrict__ BIAS,
                                                        float* __restrict__ OUT)
{
    extern __shared__ char smem[];
    constexpr int NC = KDIM / KC;
    constexpr int NBLK = NOUT / TN;
    static_assert(NC >= STAGES - 1, "priming must not exceed chunk count");

    uint32_t sb = smem_u32(smem);
    int tid = threadIdx.x, wid = tid >> 5, lane = tid & 31;

    // warp layout: 2 (M) x 4 (N); warp tile 64x32
    int wm = (wid >> 2) * 64;
    int wn = (wid & 3) * 32;
    int a_row = lane & 15;
    uint32_t a_col = (lane >> 4) * 16;                  // byte
    int b_row = wn + ((lane >> 4) << 3) + (lane & 7);   // + p*16
    uint32_t b_col = ((lane >> 3) & 1) * 16;
    int rbase = wm + (lane >> 2);
    int cbase = wn + 2 * (lane & 3);

    int lr = tid >> 3, lseg = tid & 7;   // cp.async: 32 rows x 8 segs per pass of 256 threads
    const long* s_abase = (const long*)(smem + SM_ABASE);

    int total_mt = g_tile_start[NE];
    int total = total_mt * NBLK;

    for (int idx = blockIdx.x; idx < total; idx += gridDim.x) {
        int bt = idx % total_mt;
        int n0 = (idx / total_mt) * TN;

        int e = 0;
        while (bt >= g_tile_start[e + 1]) e++;
        int m0  = (bt - g_tile_start[e]) * TM;
        int cnt = g_cnt[e];
        int off = g_off[e];

        if (tid < TM) {
            int am = m0 + tid;
            bool v = am < cnt;
            int tok = v ? g_perm[off + am] : 0;
            long rowb;
            if (FIRST) rowb = (long)tok * (KDIM * 2);
            else       rowb = (long)(off + (v ? am : 0)) * (KDIM * 2);
            ((long*)(smem + SM_ABASE))[tid] = rowb;
            ((int*)(smem + SM_TOK))[tid] = tok;
        }
        if (tid < TN) ((float*)(smem + SM_BIAS))[tid] = BIAS[e * NOUT + n0 + tid];

        const char* A = FIRST ? (const char*)g_xh : (const char*)g_hh;
        const char* B = (FIRST ? (const char*)g_w1h : (const char*)g_w2h)
                        + ((size_t)(e * NOUT + n0)) * (KDIM * 2);

        __syncthreads();   // abase table ready

        auto load_chunk = [&](int c, int s) {
            long k0b = (long)c * (KC * 2);
            uint32_t base = sb + s * STAGE_BYTES;
            #pragma unroll
            for (int i = 0; i < 4; i++) {                 // A: 128 rows
                int r = lr + i * 32;
                uint32_t d = swz(r * 128 + lseg * 16);
                cp_async16(base + d, A + s_abase[r] + k0b + lseg * 16);
            }
            #pragma unroll
            for (int i = 0; i < 4; i++) {                 // B: 128 rows
                int r = lr + i * 32;
                uint32_t d = swz(r * 128 + lseg * 16);
                cp_async16(base + 16384 + d, B + (long)r * (KDIM * 2) + k0b + lseg * 16);
            }
        };

        // prime STAGES-1 chunks
        #pragma unroll
        for (int i = 0; i < STAGES - 1; i++) {
            load_chunk(i, i);
            CP_COMMIT();
        }

        float acc[4][4][4];
        #pragma unroll
        for (int i = 0; i < 4; i++)
            #pragma unroll
            for (int j = 0; j < 4; j++)
                #pragma unroll
                for (int k = 0; k < 4; k++) acc[i][j][k] = 0.f;

        uint32_t afr[2][4][4], bfr[2][4][2];

        auto load_frags = [&](int ks, int buf, uint32_t ab, uint32_t bb) {
            uint32_t kb = (uint32_t)ks * 32;
            #pragma unroll
            for (int f = 0; f < 4; f++)
                ldsm4(afr[buf][f], ab + swz((wm + f * 16 + a_row) * 128 + kb + a_col));
            #pragma unroll
            for (int p = 0; p < 2; p++) {
                uint32_t r[4];
                ldsm4(r, bb + swz((b_row + p * 16) * 128 + kb + b_col));
                bfr[buf][2 * p][0] = r[0]; bfr[buf][2 * p][1] = r[1];
                bfr[buf][2 * p + 1][0] = r[2]; bfr[buf][2 * p + 1][1] = r[3];
            }
        };

        for (int c = 0; c < NC; c++) {
            int s = c % STAGES;
            CP_WAITP();            // exactly STAGES-1 groups pending -> chunk c resident
            __syncthreads();       // all warps done with chunk c-1: its stage is free

            // issue next gmem load FIRST, into the just-freed stage
            if (c + STAGES - 1 < NC)
                load_chunk(c + STAGES - 1, (c + STAGES - 1) % STAGES);
            CP_COMMIT();           // dummy commit keeps the pending-count invariant

            uint32_t ab = sb + s * STAGE_BYTES;
            uint32_t bb = ab + 16384;

            load_frags(0, 0, ab, bb);
            #pragma unroll
            for (int ks = 0; ks < 4; ks++) {
                if (ks < 3) load_frags(ks + 1, (ks + 1) & 1, ab, bb);   // overlap ldsm with mma
                int cur = ks & 1;
                #pragma unroll
                for (int f = 0; f < 4; f++)
                    #pragma unroll
                    for (int g = 0; g < 4; g++)
                        mma16816(acc[f][g], afr[cur][f], bfr[cur][g]);
            }
        }
        CP_WAIT0();

        // ---- epilogue ----
        const float* sbias = (const float*)(smem + SM_BIAS);
        const int* s_tok = (const int*)(smem + SM_TOK);

        #pragma unroll
        for (int f = 0; f < 4; f++) {
            #pragma unroll
            for (int half = 0; half < 2; half++) {
                int lrow = rbase + f * 16 + half * 8;
                if (m0 + lrow >= cnt) continue;
                if (FIRST) {
                    size_t hrow = (size_t)(off + m0 + lrow) * H_DIM + n0;
                    #pragma unroll
                    for (int g = 0; g < 4; g++) {
                        int col = cbase + g * 8;
                        float v0 = fmaxf(acc[f][g][2 * half]     + sbias[col],     0.f);
                        float v1 = fmaxf(acc[f][g][2 * half + 1] + sbias[col + 1], 0.f);
                        *(__half2*)(g_hh + hrow + col) = __floats2half2_rn(v0, v1);
                    }
                } else {
                    int tok = s_tok[lrow];
                    float gv = g_gate_val[tok];
                    float* orow = OUT + (size_t)tok * D_IN + n0;
                    #pragma unroll
                    for (int g = 0; g < 4; g++) {
                        int col = cbase + g * 8;
                        float2 o;
                        o.x = (acc[f][g][2 * half]     + sbias[col])     * gv;
                        o.y = (acc[f][g][2 * half + 1] + sbias[col + 1]) * gv;
                        *(float2*)(orow + col) = o;
                    }
                }
            }
        }
        __syncthreads();   // smem tables reused next iteration
    }
}

// ---------------- launch ----------------
extern "C" void kernel_launch(void* const* d_in, const int* in_sizes, int n_in,
                              void* d_out, int out_size)
{
    const float* x   = (const float*)d_in[0];
    const float* emb = (const float*)d_in[1];
    const float* rw  = (const float*)d_in[2];
    const float* w1  = (const float*)d_in[3];
    const float* b1  = (const float*)d_in[4];
    const float* w2  = (const float*)d_in[5];
    const float* b2  = (const float*)d_in[6];
    float* out = (float*)d_out;

    int nsm = 148;
    cudaDeviceGetAttribute(&nsm, cudaDevAttrMultiProcessorCount, 0);

    cudaFuncSetAttribute(moe_gemm<D_IN, H_DIM, true>,
                         cudaFuncAttributeMaxDynamicSharedMemorySize, SMEM_DYN);
    cudaFuncSetAttribute(moe_gemm<H_DIM, D_IN, false>,
                         cudaFuncAttributeMaxDynamicSharedMemorySize, SMEM_DYN);

    router_kernel<<<RBLK, 256>>>(x, emb, rw, (const float4*)w1, (const float4*)w2);
    finalize_kernel<<<1, 256>>>(out, out_size);
    scatter_kernel<<<N_TOK / 256, 256>>>();
    moe_gemm<D_IN, H_DIM, true><<<nsm, NTHREADS, SMEM_DYN>>>(b1, nullptr);
    moe_gemm<H_DIM, D_IN, false><<<nsm, NTHREADS, SMEM_DYN>>>(b2, out);
}

// round 15
// speedup vs baseline: 1.1418x; 1.1418x over previous
#include <cuda_runtime.h>
#include <cuda_fp16.h>
#include <cstdint>

// ---------------- Problem constants ----------------
#define N_TOK (16 * 2048)   // 32768 tokens
#define D_IN  512
#define E_DIM 256
#define H_DIM 1024
#define NE    4
#define RIN   (E_DIM + D_IN)
#define EPSV  1e-10f

// ---------------- GEMM tiling ----------------
#define TM 128
#define TN 128
#define KC 64                         // K elements per chunk (64 fp16 = 128B/row)
#define STAGES 3
#define NTHREADS 256

#define RTOK_PER_BLK 8
#define RBLK (N_TOK / RTOK_PER_BLK)

// ---------------- Shared memory layout ----------------
// Per stage: A 16K | B 16K = 32K; 3 stages = 96K; 2 CTAs/SM -> ~196K more tables
#define STAGE_BYTES 32768
#define SM_BIAS  (STAGES * STAGE_BYTES)          // 98304: 128 floats
#define SM_ABASE (SM_BIAS + 512)                 // 128 x int64 row byte offsets
#define SM_TOK   (SM_ABASE + 1024)               // 128 x int
#define SMEM_DYN (SM_TOK + 512)                  // 100352 bytes (x2 CTA = 200704)

// ---------------- Device scratch ----------------
__device__ int   g_gate_idx[N_TOK];
__device__ float g_gate_val[N_TOK];
__device__ int   g_perm[N_TOK + 128];
__device__ int   g_cnt[NE];
__device__ int   g_cur[NE];
__device__ int   g_off[NE + 1];
__device__ int   g_tile_start[NE + 1];
__device__ float g_part_l1[RBLK];
__device__ float g_part_imp[RBLK * NE];

__device__ __half g_xh[(size_t)N_TOK * D_IN];
__device__ __half g_w1h[(size_t)NE * H_DIM * D_IN];
__device__ __half g_w2h[(size_t)NE * D_IN * H_DIM];
__device__ __half g_hh[(size_t)(N_TOK + 128) * H_DIM];

// ---------------- PTX helpers (baseline ISA only) ----------------
__device__ __forceinline__ uint32_t smem_u32(const void* p) {
    uint32_t a;
    asm("{ .reg .u64 t; cvta.to.shared.u64 t, %1; cvt.u32.u64 %0, t; }" : "=r"(a) : "l"(p));
    return a;
}
__device__ __forceinline__ void cp_async16(uint32_t dst, const void* src) {
    asm volatile("cp.async.cg.shared.global [%0], [%1], 16;" :: "r"(dst), "l"(src) : "memory");
}
#define CP_COMMIT() asm volatile("cp.async.commit_group;" ::: "memory")
// Pending groups held at STAGES-1 = 2 (dummy commits past the tail);
// wait_group 1 => the oldest group (chunk c) has completed.
#define CP_WAITP()  asm volatile("cp.async.wait_group 1;" ::: "memory")
#define CP_WAIT0()  asm volatile("cp.async.wait_group 0;" ::: "memory")

__device__ __forceinline__ void ldsm4(uint32_t* r, uint32_t addr) {
    asm volatile("ldmatrix.sync.aligned.m8n8.x4.shared.b16 {%0,%1,%2,%3}, [%4];"
        : "=r"(r[0]), "=r"(r[1]), "=r"(r[2]), "=r"(r[3]) : "r"(addr));
}
__device__ __forceinline__ void mma16816(float* c, const uint32_t* a, const uint32_t* b) {
    asm volatile(
        "mma.sync.aligned.m16n8k16.row.col.f32.f16.f16.f32 "
        "{%0,%1,%2,%3}, {%4,%5,%6,%7}, {%8,%9}, {%0,%1,%2,%3};"
        : "+f"(c[0]), "+f"(c[1]), "+f"(c[2]), "+f"(c[3])
        : "r"(a[0]), "r"(a[1]), "r"(a[2]), "r"(a[3]), "r"(b[0]), "r"(b[1]));
}
__device__ __forceinline__ uint32_t swz(uint32_t b) { return b ^ ((b >> 3) & 0x70); }

// ---------------- 1) router (+ fused x->fp16 AND w1/w2->fp16 conversion) -------
__global__ __launch_bounds__(256) void router_kernel(
    const float* __restrict__ x, const float* __restrict__ emb,
    const float* __restrict__ rw,
    const float4* __restrict__ w1g, const float4* __restrict__ w2g)
{
    __shared__ float s_rwt[NE][RIN];
    __shared__ float s_l1[RTOK_PER_BLK];
    __shared__ float s_imp[RTOK_PER_BLK][NE];

    int t = threadIdx.x;

    // fused weight conversion: one float4 per thread (4096 blk x 256 thr = 2*n4)
    {
        const int n4 = NE * H_DIM * D_IN / 4;
        int gi = blockIdx.x * 256 + t;
        if (gi == 0) {
            #pragma unroll
            for (int e = 0; e < NE; e++) { g_cnt[e] = 0; g_cur[e] = 0; }
        }
        if (gi < n4) {
            float4 v = w1g[gi];
            __half2* h = (__half2*)g_w1h;
            h[2 * gi]     = __floats2half2_rn(v.x, v.y);
            h[2 * gi + 1] = __floats2half2_rn(v.z, v.w);
        } else {
            int j = gi - n4;
            float4 v = w2g[j];
            __half2* h = (__half2*)g_w2h;
            h[2 * j]     = __floats2half2_rn(v.x, v.y);
            h[2 * j + 1] = __floats2half2_rn(v.z, v.w);
        }
    }

    for (int i = t; i < RIN * NE; i += blockDim.x) {
        int e = i / RIN, k = i % RIN;
        s_rwt[e][k] = rw[k * NE + e];
    }
    __syncthreads();

    int warp = t >> 5, lane = t & 31;
    int tok = blockIdx.x * RTOK_PER_BLK + warp;

    float acc0 = 0.f, acc1 = 0.f, acc2 = 0.f, acc3 = 0.f;
    const float4* er4 = (const float4*)(emb + (size_t)tok * E_DIM);
    const float4* xr4 = (const float4*)(x   + (size_t)tok * D_IN);
    __half2* xh2 = (__half2*)(g_xh + (size_t)tok * D_IN);

    const float* w0 = s_rwt[0];
    const float* w1 = s_rwt[1];
    const float* w2 = s_rwt[2];
    const float* w3 = s_rwt[3];

    #pragma unroll
    for (int i = 0; i < E_DIM / 128; i++) {
        int q = lane + 32 * i;
        float4 v = er4[q];
        int k = 4 * q;
        acc0 += v.x * w0[k] + v.y * w0[k + 1] + v.z * w0[k + 2] + v.w * w0[k + 3];
        acc1 += v.x * w1[k] + v.y * w1[k + 1] + v.z * w1[k + 2] + v.w * w1[k + 3];
        acc2 += v.x * w2[k] + v.y * w2[k + 1] + v.z * w2[k + 2] + v.w * w2[k + 3];
        acc3 += v.x * w3[k] + v.y * w3[k + 1] + v.z * w3[k + 2] + v.w * w3[k + 3];
    }
    #pragma unroll
    for (int i = 0; i < D_IN / 128; i++) {
        int q = lane + 32 * i;
        float4 v = xr4[q];
        int k = E_DIM + 4 * q;
        acc0 += v.x * w0[k] + v.y * w0[k + 1] + v.z * w0[k + 2] + v.w * w0[k + 3];
        acc1 += v.x * w1[k] + v.y * w1[k + 1] + v.z * w1[k + 2] + v.w * w1[k + 3];
        acc2 += v.x * w2[k] + v.y * w2[k + 1] + v.z * w2[k + 2] + v.w * w2[k + 3];
        acc3 += v.x * w3[k] + v.y * w3[k + 1] + v.z * w3[k + 2] + v.w * w3[k + 3];
        xh2[2 * q]     = __floats2half2_rn(v.x, v.y);
        xh2[2 * q + 1] = __floats2half2_rn(v.z, v.w);
    }

    #pragma unroll
    for (int o = 16; o; o >>= 1) {
        acc0 += __shfl_xor_sync(0xFFFFFFFFu, acc0, o);
        acc1 += __shfl_xor_sync(0xFFFFFFFFu, acc1, o);
        acc2 += __shfl_xor_sync(0xFFFFFFFFu, acc2, o);
        acc3 += __shfl_xor_sync(0xFFFFFFFFu, acc3, o);
    }

    if (lane == 0) {
        float lg[NE] = {acc0, acc1, acc2, acc3};
        float m = lg[0];
        #pragma unroll
        for (int e = 1; e < NE; e++) m = fmaxf(m, lg[e]);
        float p[NE], s = 0.f;
        #pragma unroll
        for (int e = 0; e < NE; e++) { p[e] = __expf(lg[e] - m); s += p[e]; }
        float inv = 1.f / s;
        float sump = 0.f, sq = 0.f;
        float best = -1.f; int bi = 0;
        #pragma unroll
        for (int e = 0; e < NE; e++) {
            p[e] *= inv;
            sump += p[e];
            sq   += p[e] * p[e];
            if (p[e] > best) { best = p[e]; bi = e; }
        }
        g_gate_idx[tok] = bi;
        g_gate_val[tok] = best;
        atomicAdd(&g_cnt[bi], 1);
        s_l1[warp] = sump / (sqrtf(sq) + EPSV);
        #pragma unroll
        for (int e = 0; e < NE; e++) s_imp[warp][e] = p[e];
    }
    __syncthreads();
    if (t == 0) {
        float a = 0.f;
        #pragma unroll
        for (int w = 0; w < RTOK_PER_BLK; w++) a += s_l1[w];
        g_part_l1[blockIdx.x] = a;
    }
    if (t < NE) {
        float a = 0.f;
        #pragma unroll
        for (int w = 0; w < RTOK_PER_BLK; w++) a += s_imp[w][t];
        g_part_imp[blockIdx.x * NE + t] = a;
    }
}

// ---------------- 2) finalize ----------------
__global__ void finalize_kernel(float* __restrict__ out, int out_size) {
    __shared__ float sh[256];
    int t = threadIdx.x;
    float v[5] = {0.f, 0.f, 0.f, 0.f, 0.f};
    for (int b = t; b < RBLK; b += 256) {
        v[0] += g_part_l1[b];
        #pragma unroll
        for (int e = 0; e < NE; e++) v[1 + e] += g_part_imp[b * NE + e];
    }
    float res[5];
    #pragma unroll
    for (int q = 0; q < 5; q++) {
        sh[t] = v[q]; __syncthreads();
        for (int s = 128; s; s >>= 1) {
            if (t < s) sh[t] += sh[t + s];
            __syncthreads();
        }
        res[q] = sh[0];
        __syncthreads();
    }
    if (t == 0) {
        float l1 = res[0] / (float)N_TOK;
        float mean = (res[1] + res[2] + res[3] + res[4]) * 0.25f;
        float var = 0.f;
        #pragma unroll
        for (int e = 0; e < NE; e++) {
            float d = res[1 + e] - mean;
            var += d * d;
        }
        var *= 0.25f;
        float imp = var / (mean * mean + EPSV);
        if (out_size >= N_TOK * D_IN + 2) {
            out[N_TOK * D_IN]     = l1;
            out[N_TOK * D_IN + 1] = imp;
        }
        int s = 0, ts = 0;
        #pragma unroll
        for (int e = 0; e < NE; e++) {
            g_off[e] = s;
            g_tile_start[e] = ts;
            s  += g_cnt[e];
            ts += (g_cnt[e] + TM - 1) / TM;
        }
        g_off[NE] = s;
        g_tile_start[NE] = ts;
    }
}

// ---------------- 3) scatter (warp-aggregated atomics) ----------------
__global__ void scatter_kernel() {
    int t = blockIdx.x * blockDim.x + threadIdx.x;
    int lane = threadIdx.x & 31;
    int e = g_gate_idx[t];
    #pragma unroll
    for (int ei = 0; ei < NE; ei++) {
        unsigned m = __ballot_sync(0xFFFFFFFFu, e == ei);
        if (e == ei) {
            int leader = __ffs(m) - 1;
            int rank = __popc(m & ((1u << lane) - 1));
            int base = 0;
            if (lane == leader) base = atomicAdd(&g_cur[ei], __popc(m));
            base = __shfl_sync(m, base, leader);
            g_perm[g_off[ei] + base + rank] = t;
        }
    }
}

// ---------------- 4/5) persistent fp16 grouped GEMM via mma.sync ----------------
// 128x128 CTA tile, 8 warps (2 M x 4 N), warp tile 64x32, 3-stage cp.async
// pipeline, 2 CTAs per SM (decoupled barrier phases cover each other's stalls).
// FIRST:  H = relu(X[perm] @ W1^T + b1)  (fp16 out)   KDIM=512,  NOUT=1024
// !FIRST: out[tok] = gate * (H @ W2^T + b2)  (f32)    KDIM=1024, NOUT=512
template <int KDIM, int NOUT, bool FIRST>
__global__ __launch_bounds__(NTHREADS, 2) void moe_gemm(const float* __restrict__ BIAS,
                                                        float* __restrict__ OUT)
{
    extern __shared__ char smem[];
    constexpr int NC = KDIM / KC;
    constexpr int NBLK = NOUT / TN;
    static_assert(NC >= STAGES - 1, "priming must not exceed chunk count");

    uint32_t sb = smem_u32(smem);
    int tid = threadIdx.x, wid = tid >> 5, lane = tid & 31;

    // warp layout: 2 (M) x 4 (N); warp tile 64x32
    int wm = (wid >> 2) * 64;
    int wn = (wid & 3) * 32;
    int a_row = lane & 15;
    uint32_t a_col = (lane >> 4) * 16;                  // byte
    int b_row = wn + ((lane >> 4) << 3) + (lane & 7);   // + p*16
    uint32_t b_col = ((lane >> 3) & 1) * 16;
    int rbase = wm + (lane >> 2);
    int cbase = wn + 2 * (lane & 3);

    int lr = tid >> 3, lseg = tid & 7;   // cp.async: 32 rows x 8 segs per pass of 256 threads
    const long* s_abase = (const long*)(smem + SM_ABASE);

    int total_mt = g_tile_start[NE];
    int total = total_mt * NBLK;

    for (int idx = blockIdx.x; idx < total; idx += gridDim.x) {
        int bt = idx % total_mt;
        int n0 = (idx / total_mt) * TN;

        int e = 0;
        while (bt >= g_tile_start[e + 1]) e++;
        int m0  = (bt - g_tile_start[e]) * TM;
        int cnt = g_cnt[e];
        int off = g_off[e];

        if (tid < TM) {
            int am = m0 + tid;
            bool v = am < cnt;
            int tok = v ? g_perm[off + am] : 0;
            long rowb;
            if (FIRST) rowb = (long)tok * (KDIM * 2);
            else       rowb = (long)(off + (v ? am : 0)) * (KDIM * 2);
            ((long*)(smem + SM_ABASE))[tid] = rowb;
            ((int*)(smem + SM_TOK))[tid] = tok;
        }
        if (tid < TN) ((float*)(smem + SM_BIAS))[tid] = BIAS[e * NOUT + n0 + tid];

        const char* A = FIRST ? (const char*)g_xh : (const char*)g_hh;
        const char* B = (FIRST ? (const char*)g_w1h : (const char*)g_w2h)
                        + ((size_t)(e * NOUT + n0)) * (KDIM * 2);

        __syncthreads();   // abase table ready

        auto load_chunk = [&](int c, int s) {
            long k0b = (long)c * (KC * 2);
            uint32_t base = sb + s * STAGE_BYTES;
            #pragma unroll
            for (int i = 0; i < 4; i++) {                 // A: 128 rows
                int r = lr + i * 32;
                uint32_t d = swz(r * 128 + lseg * 16);
                cp_async16(base + d, A + s_abase[r] + k0b + lseg * 16);
            }
            #pragma unroll
            for (int i = 0; i < 4; i++) {                 // B: 128 rows
                int r = lr + i * 32;
                uint32_t d = swz(r * 128 + lseg * 16);
                cp_async16(base + 16384 + d, B + (long)r * (KDIM * 2) + k0b + lseg * 16);
            }
        };

        // prime STAGES-1 chunks
        #pragma unroll
        for (int i = 0; i < STAGES - 1; i++) {
            load_chunk(i, i);
            CP_COMMIT();
        }

        float acc[4][4][4];
        #pragma unroll
        for (int i = 0; i < 4; i++)
            #pragma unroll
            for (int j = 0; j < 4; j++)
                #pragma unroll
                for (int k = 0; k < 4; k++) acc[i][j][k] = 0.f;

        for (int c = 0; c < NC; c++) {
            int s = c % STAGES;
            CP_WAITP();            // exactly STAGES-1 groups pending -> chunk c resident
            __syncthreads();       // all warps done with chunk c-1: its stage is free

            // issue next gmem load FIRST, into the just-freed stage
            if (c + STAGES - 1 < NC)
                load_chunk(c + STAGES - 1, (c + STAGES - 1) % STAGES);
            CP_COMMIT();           // dummy commit keeps the pending-count invariant

            uint32_t ab = sb + s * STAGE_BYTES;
            uint32_t bb = ab + 16384;

            #pragma unroll
            for (int ks = 0; ks < 4; ks++) {
                uint32_t kb = ks * 32;   // 16 elems * 2B
                uint32_t a[4][4], b[4][2];
                #pragma unroll
                for (int f = 0; f < 4; f++)
                    ldsm4(a[f], ab + swz((wm + f * 16 + a_row) * 128 + kb + a_col));
                #pragma unroll
                for (int p = 0; p < 2; p++) {
                    uint32_t r[4];
                    ldsm4(r, bb + swz((b_row + p * 16) * 128 + kb + b_col));
                    b[2 * p][0] = r[0]; b[2 * p][1] = r[1];
                    b[2 * p + 1][0] = r[2]; b[2 * p + 1][1] = r[3];
                }
                #pragma unroll
                for (int f = 0; f < 4; f++)
                    #pragma unroll
                    for (int g = 0; g < 4; g++)
                        mma16816(acc[f][g], a[f], b[g]);
            }
        }
        CP_WAIT0();

        // ---- epilogue ----
        const float* sbias = (const float*)(smem + SM_BIAS);
        const int* s_tok = (const int*)(smem + SM_TOK);

        #pragma unroll
        for (int f = 0; f < 4; f++) {
            #pragma unroll
            for (int half = 0; half < 2; half++) {
                int lrow = rbase + f * 16 + half * 8;
                if (m0 + lrow >= cnt) continue;
                if (FIRST) {
                    size_t hrow = (size_t)(off + m0 + lrow) * H_DIM + n0;
                    #pragma unroll
                    for (int g = 0; g < 4; g++) {
                        int col = cbase + g * 8;
                        float v0 = fmaxf(acc[f][g][2 * half]     + sbias[col],     0.f);
                        float v1 = fmaxf(acc[f][g][2 * half + 1] + sbias[col + 1], 0.f);
                        *(__half2*)(g_hh + hrow + col) = __floats2half2_rn(v0, v1);
                    }
                } else {
                    int tok = s_tok[lrow];
                    float gv = g_gate_val[tok];
                    float* orow = OUT + (size_t)tok * D_IN + n0;
                    #pragma unroll
                    for (int g = 0; g < 4; g++) {
                        int col = cbase + g * 8;
                        float2 o;
                        o.x = (acc[f][g][2 * half]     + sbias[col])     * gv;
                        o.y = (acc[f][g][2 * half + 1] + sbias[col + 1]) * gv;
                        *(float2*)(orow + col) = o;
                    }
                }
            }
        }
        __syncthreads();   // smem tables reused next iteration
    }
}

// ---------------- launch ----------------
extern "C" void kernel_launch(void* const* d_in, const int* in_sizes, int n_in,
                              void* d_out, int out_size)
{
    const float* x   = (const float*)d_in[0];
    const float* emb = (const float*)d_in[1];
    const float* rw  = (const float*)d_in[2];
    const float* w1  = (const float*)d_in[3];
    const float* b1  = (const float*)d_in[4];
    const float* w2  = (const float*)d_in[5];
    const float* b2  = (const float*)d_in[6];
    float* out = (float*)d_out;

    int nsm = 148;
    cudaDeviceGetAttribute(&nsm, cudaDevAttrMultiProcessorCount, 0);

    cudaFuncSetAttribute(moe_gemm<D_IN, H_DIM, true>,
                         cudaFuncAttributeMaxDynamicSharedMemorySize, SMEM_DYN);
    cudaFuncSetAttribute(moe_gemm<H_DIM, D_IN, false>,
                         cudaFuncAttributeMaxDynamicSharedMemorySize, SMEM_DYN);

    router_kernel<<<RBLK, 256>>>(x, emb, rw, (const float4*)w1, (const float4*)w2);
    finalize_kernel<<<1, 256>>>(out, out_size);
    scatter_kernel<<<N_TOK / 256, 256>>>();
    moe_gemm<D_IN, H_DIM, true><<<2 * nsm, NTHREADS, SMEM_DYN>>>(b1, nullptr);
    moe_gemm<H_DIM, D_IN, false><<<2 * nsm, NTHREADS, SMEM_DYN>>>(b2, out);
}

// round 16
// speedup vs baseline: 1.1838x; 1.0368x over previous
#include <cuda_runtime.h>
#include <cuda_fp16.h>
#include <cstdint>

// ---------------- Problem constants ----------------
#define N_TOK (16 * 2048)   // 32768 tokens
#define D_IN  512
#define E_DIM 256
#define H_DIM 1024
#define NE    4
#define RIN   (E_DIM + D_IN)
#define EPSV  1e-10f

// ---------------- GEMM tiling ----------------
#define TM 128
#define TN 128
#define KC 64                         // K elements per chunk (64 fp16 = 128B/row)
#define STAGES 3
#define NTHREADS 128                  // 4 warps (2x2), warp tile 64x64

#define RTOK_PER_BLK 8
#define RBLK (N_TOK / RTOK_PER_BLK)

// ---------------- Shared memory layout ----------------
// Per stage: A 16K | B 16K = 32K; 3 stages = 96K; 2 CTAs/SM
#define STAGE_BYTES 32768
#define SM_BIAS  (STAGES * STAGE_BYTES)          // 98304: 128 floats
#define SM_ABASE (SM_BIAS + 512)                 // 128 x int64 row byte offsets
#define SM_TOK   (SM_ABASE + 1024)               // 128 x int
#define SMEM_DYN (SM_TOK + 512)                  // 100352 bytes (x2 CTA = 200704)

// ---------------- Device scratch ----------------
__device__ int   g_gate_idx[N_TOK];
__device__ float g_gate_val[N_TOK];
__device__ int   g_perm[N_TOK + 128];
__device__ int   g_cnt[NE];
__device__ int   g_cur[NE];
__device__ int   g_off[NE + 1];
__device__ int   g_tile_start[NE + 1];
__device__ float g_part_l1[RBLK];
__device__ float g_part_imp[RBLK * NE];

__device__ __half g_xh[(size_t)N_TOK * D_IN];
__device__ __half g_w1h[(size_t)NE * H_DIM * D_IN];
__device__ __half g_w2h[(size_t)NE * D_IN * H_DIM];
__device__ __half g_hh[(size_t)(N_TOK + 128) * H_DIM];

// ---------------- PTX helpers (baseline ISA only) ----------------
__device__ __forceinline__ uint32_t smem_u32(const void* p) {
    uint32_t a;
    asm("{ .reg .u64 t; cvta.to.shared.u64 t, %1; cvt.u32.u64 %0, t; }" : "=r"(a) : "l"(p));
    return a;
}
__device__ __forceinline__ void cp_async16(uint32_t dst, const void* src) {
    asm volatile("cp.async.cg.shared.global [%0], [%1], 16;" :: "r"(dst), "l"(src) : "memory");
}
#define CP_COMMIT() asm volatile("cp.async.commit_group;" ::: "memory")
// Pending groups held at STAGES-1 = 2 (dummy commits past the tail);
// wait_group 1 => the oldest group (chunk c) has completed.
#define CP_WAITP()  asm volatile("cp.async.wait_group 1;" ::: "memory")
#define CP_WAIT0()  asm volatile("cp.async.wait_group 0;" ::: "memory")

__device__ __forceinline__ void ldsm4(uint32_t* r, uint32_t addr) {
    asm volatile("ldmatrix.sync.aligned.m8n8.x4.shared.b16 {%0,%1,%2,%3}, [%4];"
        : "=r"(r[0]), "=r"(r[1]), "=r"(r[2]), "=r"(r[3]) : "r"(addr));
}
__device__ __forceinline__ void mma16816(float* c, const uint32_t* a, const uint32_t* b) {
    asm volatile(
        "mma.sync.aligned.m16n8k16.row.col.f32.f16.f16.f32 "
        "{%0,%1,%2,%3}, {%4,%5,%6,%7}, {%8,%9}, {%0,%1,%2,%3};"
        : "+f"(c[0]), "+f"(c[1]), "+f"(c[2]), "+f"(c[3])
        : "r"(a[0]), "r"(a[1]), "r"(a[2]), "r"(a[3]), "r"(b[0]), "r"(b[1]));
}
__device__ __forceinline__ uint32_t swz(uint32_t b) { return b ^ ((b >> 3) & 0x70); }

// ---------------- 1) router (+ fused x->fp16 AND w1/w2->fp16 conversion) -------
__global__ __launch_bounds__(256) void router_kernel(
    const float* __restrict__ x, const float* __restrict__ emb,
    const float* __restrict__ rw,
    const float4* __restrict__ w1g, const float4* __restrict__ w2g)
{
    __shared__ float s_rwt[NE][RIN];
    __shared__ float s_l1[RTOK_PER_BLK];
    __shared__ float s_imp[RTOK_PER_BLK][NE];

    int t = threadIdx.x;

    // fused weight conversion: one float4 per thread (4096 blk x 256 thr = 2*n4)
    {
        const int n4 = NE * H_DIM * D_IN / 4;
        int gi = blockIdx.x * 256 + t;
        if (gi == 0) {
            #pragma unroll
            for (int e = 0; e < NE; e++) { g_cnt[e] = 0; g_cur[e] = 0; }
        }
        if (gi < n4) {
            float4 v = w1g[gi];
            __half2* h = (__half2*)g_w1h;
            h[2 * gi]     = __floats2half2_rn(v.x, v.y);
            h[2 * gi + 1] = __floats2half2_rn(v.z, v.w);
        } else {
            int j = gi - n4;
            float4 v = w2g[j];
            __half2* h = (__half2*)g_w2h;
            h[2 * j]     = __floats2half2_rn(v.x, v.y);
            h[2 * j + 1] = __floats2half2_rn(v.z, v.w);
        }
    }

    for (int i = t; i < RIN * NE; i += blockDim.x) {
        int e = i / RIN, k = i % RIN;
        s_rwt[e][k] = rw[k * NE + e];
    }
    __syncthreads();

    int warp = t >> 5, lane = t & 31;
    int tok = blockIdx.x * RTOK_PER_BLK + warp;

    float acc0 = 0.f, acc1 = 0.f, acc2 = 0.f, acc3 = 0.f;
    const float4* er4 = (const float4*)(emb + (size_t)tok * E_DIM);
    const float4* xr4 = (const float4*)(x   + (size_t)tok * D_IN);
    __half2* xh2 = (__half2*)(g_xh + (size_t)tok * D_IN);

    const float* w0 = s_rwt[0];
    const float* w1 = s_rwt[1];
    const float* w2 = s_rwt[2];
    const float* w3 = s_rwt[3];

    #pragma unroll
    for (int i = 0; i < E_DIM / 128; i++) {
        int q = lane + 32 * i;
        float4 v = er4[q];
        int k = 4 * q;
        acc0 += v.x * w0[k] + v.y * w0[k + 1] + v.z * w0[k + 2] + v.w * w0[k + 3];
        acc1 += v.x * w1[k] + v.y * w1[k + 1] + v.z * w1[k + 2] + v.w * w1[k + 3];
        acc2 += v.x * w2[k] + v.y * w2[k + 1] + v.z * w2[k + 2] + v.w * w2[k + 3];
        acc3 += v.x * w3[k] + v.y * w3[k + 1] + v.z * w3[k + 2] + v.w * w3[k + 3];
    }
    #pragma unroll
    for (int i = 0; i < D_IN / 128; i++) {
        int q = lane + 32 * i;
        float4 v = xr4[q];
        int k = E_DIM + 4 * q;
        acc0 += v.x * w0[k] + v.y * w0[k + 1] + v.z * w0[k + 2] + v.w * w0[k + 3];
        acc1 += v.x * w1[k] + v.y * w1[k + 1] + v.z * w1[k + 2] + v.w * w1[k + 3];
        acc2 += v.x * w2[k] + v.y * w2[k + 1] + v.z * w2[k + 2] + v.w * w2[k + 3];
        acc3 += v.x * w3[k] + v.y * w3[k + 1] + v.z * w3[k + 2] + v.w * w3[k + 3];
        xh2[2 * q]     = __floats2half2_rn(v.x, v.y);
        xh2[2 * q + 1] = __floats2half2_rn(v.z, v.w);
    }

    #pragma unroll
    for (int o = 16; o; o >>= 1) {
        acc0 += __shfl_xor_sync(0xFFFFFFFFu, acc0, o);
        acc1 += __shfl_xor_sync(0xFFFFFFFFu, acc1, o);
        acc2 += __shfl_xor_sync(0xFFFFFFFFu, acc2, o);
        acc3 += __shfl_xor_sync(0xFFFFFFFFu, acc3, o);
    }

    if (lane == 0) {
        float lg[NE] = {acc0, acc1, acc2, acc3};
        float m = lg[0];
        #pragma unroll
        for (int e = 1; e < NE; e++) m = fmaxf(m, lg[e]);
        float p[NE], s = 0.f;
        #pragma unroll
        for (int e = 0; e < NE; e++) { p[e] = __expf(lg[e] - m); s += p[e]; }
        float inv = 1.f / s;
        float sump = 0.f, sq = 0.f;
        float best = -1.f; int bi = 0;
        #pragma unroll
        for (int e = 0; e < NE; e++) {
            p[e] *= inv;
            sump += p[e];
            sq   += p[e] * p[e];
            if (p[e] > best) { best = p[e]; bi = e; }
        }
        g_gate_idx[tok] = bi;
        g_gate_val[tok] = best;
        atomicAdd(&g_cnt[bi], 1);
        s_l1[warp] = sump / (sqrtf(sq) + EPSV);
        #pragma unroll
        for (int e = 0; e < NE; e++) s_imp[warp][e] = p[e];
    }
    __syncthreads();
    if (t == 0) {
        float a = 0.f;
        #pragma unroll
        for (int w = 0; w < RTOK_PER_BLK; w++) a += s_l1[w];
        g_part_l1[blockIdx.x] = a;
    }
    if (t < NE) {
        float a = 0.f;
        #pragma unroll
        for (int w = 0; w < RTOK_PER_BLK; w++) a += s_imp[w][t];
        g_part_imp[blockIdx.x * NE + t] = a;
    }
}

// ---------------- 2) finalize ----------------
__global__ void finalize_kernel(float* __restrict__ out, int out_size) {
    __shared__ float sh[256];
    int t = threadIdx.x;
    float v[5] = {0.f, 0.f, 0.f, 0.f, 0.f};
    for (int b = t; b < RBLK; b += 256) {
        v[0] += g_part_l1[b];
        #pragma unroll
        for (int e = 0; e < NE; e++) v[1 + e] += g_part_imp[b * NE + e];
    }
    float res[5];
    #pragma unroll
    for (int q = 0; q < 5; q++) {
        sh[t] = v[q]; __syncthreads();
        for (int s = 128; s; s >>= 1) {
            if (t < s) sh[t] += sh[t + s];
            __syncthreads();
        }
        res[q] = sh[0];
        __syncthreads();
    }
    if (t == 0) {
        float l1 = res[0] / (float)N_TOK;
        float mean = (res[1] + res[2] + res[3] + res[4]) * 0.25f;
        float var = 0.f;
        #pragma unroll
        for (int e = 0; e < NE; e++) {
            float d = res[1 + e] - mean;
            var += d * d;
        }
        var *= 0.25f;
        float imp = var / (mean * mean + EPSV);
        if (out_size >= N_TOK * D_IN + 2) {
            out[N_TOK * D_IN]     = l1;
            out[N_TOK * D_IN + 1] = imp;
        }
        int s = 0, ts = 0;
        #pragma unroll
        for (int e = 0; e < NE; e++) {
            g_off[e] = s;
            g_tile_start[e] = ts;
            s  += g_cnt[e];
            ts += (g_cnt[e] + TM - 1) / TM;
        }
        g_off[NE] = s;
        g_tile_start[NE] = ts;
    }
}

// ---------------- 3) scatter (warp-aggregated atomics) ----------------
__global__ void scatter_kernel() {
    int t = blockIdx.x * blockDim.x + threadIdx.x;
    int lane = threadIdx.x & 31;
    int e = g_gate_idx[t];
    #pragma unroll
    for (int ei = 0; ei < NE; ei++) {
        unsigned m = __ballot_sync(0xFFFFFFFFu, e == ei);
        if (e == ei) {
            int leader = __ffs(m) - 1;
            int rank = __popc(m & ((1u << lane) - 1));
            int base = 0;
            if (lane == leader) base = atomicAdd(&g_cur[ei], __popc(m));
            base = __shfl_sync(m, base, leader);
            g_perm[g_off[ei] + base + rank] = t;
        }
    }
}

// ---------------- 4/5) persistent fp16 grouped GEMM via mma.sync ----------------
// 128x128 CTA tile, 4 warps (2 M x 2 N), warp tile 64x64, 3-stage cp.async
// pipeline, 2 CTAs per SM. 64x64 warp tile = 32 FLOP per smem byte (1.5x the
// 64x32 tile) and 32 back-to-back HMMAs per ldsm batch.
// FIRST:  H = relu(X[perm] @ W1^T + b1)  (fp16 out)   KDIM=512,  NOUT=1024
// !FIRST: out[tok] = gate * (H @ W2^T + b2)  (f32)    KDIM=1024, NOUT=512
template <int KDIM, int NOUT, bool FIRST>
__global__ __launch_bounds__(NTHREADS, 2) void moe_gemm(const float* __restrict__ BIAS,
                                                        float* __restrict__ OUT)
{
    extern __shared__ char smem[];
    constexpr int NC = KDIM / KC;
    constexpr int NBLK = NOUT / TN;
    static_assert(NC >= STAGES - 1, "priming must not exceed chunk count");

    uint32_t sb = smem_u32(smem);
    int tid = threadIdx.x, wid = tid >> 5, lane = tid & 31;

    // warp layout: 2 (M) x 2 (N); warp tile 64x64
    int wm = (wid >> 1) * 64;
    int wn = (wid & 1) * 64;
    int a_row = lane & 15;
    uint32_t a_col = (lane >> 4) * 16;                  // byte
    int b_row = wn + ((lane >> 4) << 3) + (lane & 7);   // + p*16, p=0..3
    uint32_t b_col = ((lane >> 3) & 1) * 16;
    int rbase = wm + (lane >> 2);
    int cbase = wn + 2 * (lane & 3);

    int lr = tid >> 3, lseg = tid & 7;   // cp.async: 16 rows x 8 segs per pass of 128 threads
    const long* s_abase = (const long*)(smem + SM_ABASE);

    int total_mt = g_tile_start[NE];
    int total = total_mt * NBLK;

    for (int idx = blockIdx.x; idx < total; idx += gridDim.x) {
        int bt = idx % total_mt;
        int n0 = (idx / total_mt) * TN;

        int e = 0;
        while (bt >= g_tile_start[e + 1]) e++;
        int m0  = (bt - g_tile_start[e]) * TM;
        int cnt = g_cnt[e];
        int off = g_off[e];

        if (tid < TM) {
            int am = m0 + tid;
            bool v = am < cnt;
            int tok = v ? g_perm[off + am] : 0;
            long rowb;
            if (FIRST) rowb = (long)tok * (KDIM * 2);
            else       rowb = (long)(off + (v ? am : 0)) * (KDIM * 2);
            ((long*)(smem + SM_ABASE))[tid] = rowb;
            ((int*)(smem + SM_TOK))[tid] = tok;
        }
        if (tid < TN) ((float*)(smem + SM_BIAS))[tid] = BIAS[e * NOUT + n0 + tid];

        const char* A = FIRST ? (const char*)g_xh : (const char*)g_hh;
        const char* B = (FIRST ? (const char*)g_w1h : (const char*)g_w2h)
                        + ((size_t)(e * NOUT + n0)) * (KDIM * 2);

        __syncthreads();   // abase table ready

        auto load_chunk = [&](int c, int s) {
            long k0b = (long)c * (KC * 2);
            uint32_t base = sb + s * STAGE_BYTES;
            #pragma unroll
            for (int i = 0; i < 8; i++) {                 // A: 128 rows
                int r = lr + i * 16;
                uint32_t d = swz(r * 128 + lseg * 16);
                cp_async16(base + d, A + s_abase[r] + k0b + lseg * 16);
            }
            #pragma unroll
            for (int i = 0; i < 8; i++) {                 // B: 128 rows
                int r = lr + i * 16;
                uint32_t d = swz(r * 128 + lseg * 16);
                cp_async16(base + 16384 + d, B + (long)r * (KDIM * 2) + k0b + lseg * 16);
            }
        };

        // prime STAGES-1 chunks
        #pragma unroll
        for (int i = 0; i < STAGES - 1; i++) {
            load_chunk(i, i);
            CP_COMMIT();
        }

        float acc[4][8][4];
        #pragma unroll
        for (int i = 0; i < 4; i++)
            #pragma unroll
            for (int j = 0; j < 8; j++)
                #pragma unroll
                for (int k = 0; k < 4; k++) acc[i][j][k] = 0.f;

        for (int c = 0; c < NC; c++) {
            int s = c % STAGES;
            CP_WAITP();            // exactly STAGES-1 groups pending -> chunk c resident
            __syncthreads();       // all warps done with chunk c-1: its stage is free

            // issue next gmem load FIRST, into the just-freed stage
            if (c + STAGES - 1 < NC)
                load_chunk(c + STAGES - 1, (c + STAGES - 1) % STAGES);
            CP_COMMIT();           // dummy commit keeps the pending-count invariant

            uint32_t ab = sb + s * STAGE_BYTES;
            uint32_t bb = ab + 16384;

            #pragma unroll
            for (int ks = 0; ks < 4; ks++) {
                uint32_t kb = ks * 32;   // 16 elems * 2B
                uint32_t a[4][4], b[8][2];
                #pragma unroll
                for (int f = 0; f < 4; f++)
                    ldsm4(a[f], ab + swz((wm + f * 16 + a_row) * 128 + kb + a_col));
                #pragma unroll
                for (int p = 0; p < 4; p++) {
                    uint32_t r[4];
                    ldsm4(r, bb + swz((b_row + p * 16) * 128 + kb + b_col));
                    b[2 * p][0] = r[0]; b[2 * p][1] = r[1];
                    b[2 * p + 1][0] = r[2]; b[2 * p + 1][1] = r[3];
                }
                #pragma unroll
                for (int f = 0; f < 4; f++)
                    #pragma unroll
                    for (int g = 0; g < 8; g++)
                        mma16816(acc[f][g], a[f], b[g]);
            }
        }
        CP_WAIT0();

        // ---- epilogue ----
        const float* sbias = (const float*)(smem + SM_BIAS);
        const int* s_tok = (const int*)(smem + SM_TOK);

        #pragma unroll
        for (int f = 0; f < 4; f++) {
            #pragma unroll
            for (int half = 0; half < 2; half++) {
                int lrow = rbase + f * 16 + half * 8;
                if (m0 + lrow >= cnt) continue;
                if (FIRST) {
                    size_t hrow = (size_t)(off + m0 + lrow) * H_DIM + n0;
                    #pragma unroll
                    for (int g = 0; g < 8; g++) {
                        int col = cbase + g * 8;
                        float v0 = fmaxf(acc[f][g][2 * half]     + sbias[col],     0.f);
                        float v1 = fmaxf(acc[f][g][2 * half + 1] + sbias[col + 1], 0.f);
                        *(__half2*)(g_hh + hrow + col) = __floats2half2_rn(v0, v1);
                    }
                } else {
                    int tok = s_tok[lrow];
                    float gv = g_gate_val[tok];
                    float* orow = OUT + (size_t)tok * D_IN + n0;
                    #pragma unroll
                    for (int g = 0; g < 8; g++) {
                        int col = cbase + g * 8;
                        float2 o;
                        o.x = (acc[f][g][2 * half]     + sbias[col])     * gv;
                        o.y = (acc[f][g][2 * half + 1] + sbias[col + 1]) * gv;
                        *(float2*)(orow + col) = o;
                    }
                }
            }
        }
        __syncthreads();   // smem tables reused next iteration
    }
}

// ---------------- launch ----------------
extern "C" void kernel_launch(void* const* d_in, const int* in_sizes, int n_in,
                              void* d_out, int out_size)
{
    const float* x   = (const float*)d_in[0];
    const float* emb = (const float*)d_in[1];
    const float* rw  = (const float*)d_in[2];
    const float* w1  = (const float*)d_in[3];
    const float* b1  = (const float*)d_in[4];
    const float* w2  = (const float*)d_in[5];
    const float* b2  = (const float*)d_in[6];
    float* out = (float*)d_out;

    int nsm = 148;
    cudaDeviceGetAttribute(&nsm, cudaDevAttrMultiProcessorCount, 0);

    cudaFuncSetAttribute(moe_gemm<D_IN, H_DIM, true>,
                         cudaFuncAttributeMaxDynamicSharedMemorySize, SMEM_DYN);
    cudaFuncSetAttribute(moe_gemm<H_DIM, D_IN, false>,
                         cudaFuncAttributeMaxDynamicSharedMemorySize, SMEM_DYN);

    router_kernel<<<RBLK, 256>>>(x, emb, rw, (const float4*)w1, (const float4*)w2);
    finalize_kernel<<<1, 256>>>(out, out_size);
    scatter_kernel<<<N_TOK / 256, 256>>>();
    moe_gemm<D_IN, H_DIM, true><<<2 * nsm, NTHREADS, SMEM_DYN>>>(b1, nullptr);
    moe_gemm<H_DIM, D_IN, false><<<2 * nsm, NTHREADS, SMEM_DYN>>>(b2, out);
}